// round 1
// baseline (speedup 1.0000x reference)
#include <cuda_runtime.h>
#include <cuda_bf16.h>
#include <math.h>
#include <stdint.h>

#define DIM   1024
#define HID   4096
#define NROWS 32768   // 4 * 8192 tokens

// ---------------- scratch (static __device__ — no allocations allowed) ----------------
__device__ __nv_bfloat16 g_w1q[(size_t)HID * DIM];    // quantized w1 ints as bf16
__device__ __nv_bfloat16 g_w2q[(size_t)DIM * HID];    // quantized w2 ints as bf16
__device__ __nv_bfloat16 g_aq [(size_t)NROWS * DIM];  // quantized LN(x) ints as bf16
__device__ float         g_act[(size_t)NROWS * HID];  // fp32 GELU output (pre-2nd-quant)
__device__ __nv_bfloat16 g_hq [(size_t)NROWS * HID];  // quantized hidden ints as bf16
__device__ float         g_mu  [NROWS];
__device__ float         g_rstd[NROWS];
__device__ unsigned      g_maxbits[4];  // 0: max|LN|, 1: max|w1|, 2: max|w2|, 3: max|gelu|

// ---------------- small helpers ----------------
__device__ __forceinline__ float gelu_erf(float y) {
    return 0.5f * y * (1.0f + erff(y * 0.70710678118654752440f));
}

__device__ __forceinline__ void cpasync16(void* smem, const void* gmem) {
    unsigned s = (unsigned)__cvta_generic_to_shared(smem);
    size_t   g = __cvta_generic_to_global(gmem);
    asm volatile("cp.async.cg.shared.global [%0], [%1], 16;\n" :: "r"(s), "l"(g));
}
#define CP_COMMIT() asm volatile("cp.async.commit_group;\n")
#define CP_WAIT0()  asm volatile("cp.async.wait_group 0;\n")

__device__ __forceinline__ void ldsm4(unsigned* r, const void* p) {
    unsigned a = (unsigned)__cvta_generic_to_shared(p);
    asm volatile("ldmatrix.sync.aligned.m8n8.x4.shared.b16 {%0,%1,%2,%3}, [%4];\n"
                 : "=r"(r[0]), "=r"(r[1]), "=r"(r[2]), "=r"(r[3]) : "r"(a));
}

__device__ __forceinline__ void mma16816(float* c, const unsigned* a, unsigned b0, unsigned b1) {
    asm volatile(
        "mma.sync.aligned.m16n8k16.row.col.f32.bf16.bf16.f32 "
        "{%0,%1,%2,%3}, {%4,%5,%6,%7}, {%8,%9}, {%0,%1,%2,%3};\n"
        : "+f"(c[0]), "+f"(c[1]), "+f"(c[2]), "+f"(c[3])
        : "r"(a[0]), "r"(a[1]), "r"(a[2]), "r"(a[3]), "r"(b0), "r"(b1));
}

// ---------------- init ----------------
__global__ void k_init() {
    if (threadIdx.x < 4) g_maxbits[threadIdx.x] = 0u;
}

// ---------------- per-tensor abs-max (weights) ----------------
__global__ void __launch_bounds__(256) k_maxabs(const float4* __restrict__ p, int n4, int slot) {
    float m = 0.f;
    for (int i = blockIdx.x * blockDim.x + threadIdx.x; i < n4; i += gridDim.x * blockDim.x) {
        float4 v = p[i];
        m = fmaxf(m, fmaxf(fmaxf(fabsf(v.x), fabsf(v.y)), fmaxf(fabsf(v.z), fabsf(v.w))));
    }
    #pragma unroll
    for (int o = 16; o; o >>= 1) m = fmaxf(m, __shfl_xor_sync(0xffffffffu, m, o));
    __shared__ float sm[8];
    if ((threadIdx.x & 31) == 0) sm[threadIdx.x >> 5] = m;
    __syncthreads();
    if (threadIdx.x == 0) {
        #pragma unroll
        for (int i = 1; i < 8; i++) m = fmaxf(m, sm[i]);
        m = fmaxf(m, sm[0]);
        atomicMax(&g_maxbits[slot], __float_as_uint(m));
    }
}

// ---------------- weight quantize -> bf16 integers ----------------
__global__ void __launch_bounds__(256) k_wquant(const float4* __restrict__ w, int n4, int slot) {
    __nv_bfloat16* out = (slot == 1) ? g_w1q : g_w2q;
    float s = __uint_as_float(g_maxbits[slot]);
    int i = blockIdx.x * 256 + threadIdx.x;
    if (i >= n4) return;
    float4 v = w[i];
    float q0 = rintf(fminf(fmaxf(v.x / s, -1.f), 1.f) * 127.f);
    float q1 = rintf(fminf(fmaxf(v.y / s, -1.f), 1.f) * 127.f);
    float q2 = rintf(fminf(fmaxf(v.z / s, -1.f), 1.f) * 127.f);
    float q3 = rintf(fminf(fmaxf(v.w / s, -1.f), 1.f) * 127.f);
    ushort4 u;
    u.x = __bfloat16_as_ushort(__float2bfloat16_rn(q0));
    u.y = __bfloat16_as_ushort(__float2bfloat16_rn(q1));
    u.z = __bfloat16_as_ushort(__float2bfloat16_rn(q2));
    u.w = __bfloat16_as_ushort(__float2bfloat16_rn(q3));
    ((ushort4*)out)[i] = u;
}

// ---------------- LayerNorm stats + global max|LN(x)| ----------------
__global__ void __launch_bounds__(256) k_ln(const float* __restrict__ x,
                                            const float* __restrict__ gamma,
                                            const float* __restrict__ beta) {
    int row = blockIdx.x;
    int t = threadIdx.x;  // 256 threads, 4 floats each (DIM = 1024)
    const float4* xr = (const float4*)(x + (size_t)row * DIM);
    float4 v = xr[t];
    float s1 = v.x + v.y + v.z + v.w;
    float s2 = v.x * v.x + v.y * v.y + v.z * v.z + v.w * v.w;
    #pragma unroll
    for (int o = 16; o; o >>= 1) {
        s1 += __shfl_xor_sync(0xffffffffu, s1, o);
        s2 += __shfl_xor_sync(0xffffffffu, s2, o);
    }
    __shared__ float a1[8], a2[8];
    __shared__ float s_mu, s_rstd;
    int w = t >> 5;
    if ((t & 31) == 0) { a1[w] = s1; a2[w] = s2; }
    __syncthreads();
    if (t == 0) {
        float S1 = 0.f, S2 = 0.f;
        #pragma unroll
        for (int i = 0; i < 8; i++) { S1 += a1[i]; S2 += a2[i]; }
        float mu   = S1 * (1.0f / DIM);
        float var  = S2 * (1.0f / DIM) - mu * mu;
        float rstd = rsqrtf(var + 1e-5f);
        s_mu = mu; s_rstd = rstd;
        g_mu[row] = mu; g_rstd[row] = rstd;
    }
    __syncthreads();
    float mu = s_mu, r = s_rstd;
    float4 gm = ((const float4*)gamma)[t];
    float4 bt = ((const float4*)beta)[t];
    float h0 = (v.x - mu) * r * gm.x + bt.x;
    float h1 = (v.y - mu) * r * gm.y + bt.y;
    float h2 = (v.z - mu) * r * gm.z + bt.z;
    float h3 = (v.w - mu) * r * gm.w + bt.w;
    float m = fmaxf(fmaxf(fabsf(h0), fabsf(h1)), fmaxf(fabsf(h2), fabsf(h3)));
    #pragma unroll
    for (int o = 16; o; o >>= 1) m = fmaxf(m, __shfl_xor_sync(0xffffffffu, m, o));
    if ((t & 31) == 0) a1[w] = m;
    __syncthreads();
    if (t == 0) {
        #pragma unroll
        for (int i = 1; i < 8; i++) m = fmaxf(m, a1[i]);
        m = fmaxf(m, a1[0]);
        atomicMax(&g_maxbits[0], __float_as_uint(m));
    }
}

// ---------------- activation quantize (LN recompute with cached stats) ----------------
__global__ void __launch_bounds__(256) k_aquant(const float* __restrict__ x,
                                                const float* __restrict__ gamma,
                                                const float* __restrict__ beta) {
    int i  = blockIdx.x * 256 + threadIdx.x;  // float4 index, NROWS*256 total
    int row = i >> 8;
    int c4  = i & 255;
    float s  = __uint_as_float(g_maxbits[0]);
    float mu = g_mu[row], r = g_rstd[row];
    float4 v  = ((const float4*)x)[i];
    float4 gm = ((const float4*)gamma)[c4];
    float4 bt = ((const float4*)beta)[c4];
    float h0 = (v.x - mu) * r * gm.x + bt.x;
    float h1 = (v.y - mu) * r * gm.y + bt.y;
    float h2 = (v.z - mu) * r * gm.z + bt.z;
    float h3 = (v.w - mu) * r * gm.w + bt.w;
    float q0 = rintf(fminf(fmaxf(h0 / s, -1.f), 1.f) * 127.f);
    float q1 = rintf(fminf(fmaxf(h1 / s, -1.f), 1.f) * 127.f);
    float q2 = rintf(fminf(fmaxf(h2 / s, -1.f), 1.f) * 127.f);
    float q3 = rintf(fminf(fmaxf(h3 / s, -1.f), 1.f) * 127.f);
    ushort4 u;
    u.x = __bfloat16_as_ushort(__float2bfloat16_rn(q0));
    u.y = __bfloat16_as_ushort(__float2bfloat16_rn(q1));
    u.z = __bfloat16_as_ushort(__float2bfloat16_rn(q2));
    u.w = __bfloat16_as_ushort(__float2bfloat16_rn(q3));
    ((ushort4*)g_aq)[i] = u;
}

// ---------------- hidden quantize (GELU output -> bf16 integers) ----------------
__global__ void __launch_bounds__(256) k_hquant() {
    size_t i = (size_t)blockIdx.x * 256 + threadIdx.x;  // float4 index
    float s = __uint_as_float(g_maxbits[3]);
    float4 v = ((const float4*)g_act)[i];
    float q0 = rintf(fminf(fmaxf(v.x / s, -1.f), 1.f) * 127.f);
    float q1 = rintf(fminf(fmaxf(v.y / s, -1.f), 1.f) * 127.f);
    float q2 = rintf(fminf(fmaxf(v.z / s, -1.f), 1.f) * 127.f);
    float q3 = rintf(fminf(fmaxf(v.w / s, -1.f), 1.f) * 127.f);
    ushort4 u;
    u.x = __bfloat16_as_ushort(__float2bfloat16_rn(q0));
    u.y = __bfloat16_as_ushort(__float2bfloat16_rn(q1));
    u.z = __bfloat16_as_ushort(__float2bfloat16_rn(q2));
    u.w = __bfloat16_as_ushort(__float2bfloat16_rn(q3));
    ((ushort4*)g_hq)[i] = u;
}

// ---------------- GEMM: C[M,N] = A[M,K] * B[N,K]^T, bf16-int operands, fused epilogue ----
// Tile 128x128x32, 256 threads (8 warps as 4x2), warp tile 32x64, mma.m16n8k16.
template<bool GELU, int N, int K>
__global__ void __launch_bounds__(256) k_gemm(const float* __restrict__ bias,
                                              float* __restrict__ out) {
    constexpr int KT = K / 32;
    const __nv_bfloat16* __restrict__ A = GELU ? g_aq  : g_hq;
    const __nv_bfloat16* __restrict__ B = GELU ? g_w1q : g_w2q;

    __shared__ __nv_bfloat16 As[2][128][40];  // pad to 40: conflict-free ldmatrix
    __shared__ __nv_bfloat16 Bs[2][128][40];

    const int tid  = threadIdx.x;
    const int lane = tid & 31;
    const int wid  = tid >> 5;
    const int m_w  = (wid >> 1) * 32;
    const int n_w  = (wid & 1) * 64;
    const int mBase = blockIdx.y * 128;
    const int nBase = blockIdx.x * 128;

    const __nv_bfloat16* Ag = A + (size_t)mBase * K;
    const __nv_bfloat16* Bg = B + (size_t)nBase * K;

    float acc[2][8][4];
    #pragma unroll
    for (int i = 0; i < 2; i++)
        #pragma unroll
        for (int j = 0; j < 8; j++)
            #pragma unroll
            for (int r = 0; r < 4; r++) acc[i][j][r] = 0.f;

    auto loadTile = [&](int kt, int buf) {
        int k0 = kt * 32;
        #pragma unroll
        for (int i = 0; i < 2; i++) {
            int c = tid + i * 256;
            int rr = c >> 2, cc = (c & 3) * 8;
            cpasync16(&As[buf][rr][cc], Ag + (size_t)rr * K + k0 + cc);
        }
        #pragma unroll
        for (int i = 0; i < 2; i++) {
            int c = tid + i * 256;
            int rr = c >> 2, cc = (c & 3) * 8;
            cpasync16(&Bs[buf][rr][cc], Bg + (size_t)rr * K + k0 + cc);
        }
    };

    loadTile(0, 0);
    CP_COMMIT();
    CP_WAIT0();
    __syncthreads();

    int buf = 0;
    for (int kt = 0; kt < KT; ++kt) {
        if (kt + 1 < KT) { loadTile(kt + 1, buf ^ 1); CP_COMMIT(); }
        #pragma unroll
        for (int ks = 0; ks < 2; ++ks) {
            unsigned af[2][4], bfr[4][4];
            #pragma unroll
            for (int mi = 0; mi < 2; mi++)
                ldsm4(af[mi], &As[buf][m_w + mi * 16 + (lane & 15)][ks * 16 + (lane >> 4) * 8]);
            #pragma unroll
            for (int ni = 0; ni < 4; ni++)
                ldsm4(bfr[ni], &Bs[buf][n_w + ni * 16 + (lane & 15)][ks * 16 + (lane >> 4) * 8]);
            #pragma unroll
            for (int mi = 0; mi < 2; mi++)
                #pragma unroll
                for (int nj = 0; nj < 8; nj++)
                    mma16816(acc[mi][nj], af[mi], bfr[nj >> 1][nj & 1], bfr[nj >> 1][2 + (nj & 1)]);
        }
        if (kt + 1 < KT) CP_WAIT0();
        __syncthreads();
        buf ^= 1;
    }

    // ---- epilogue ----
    if (GELU) {
        float sA = __uint_as_float(g_maxbits[0]);
        float sW = __uint_as_float(g_maxbits[1]);
        float scale = sA * sW * (1.0f / 16129.0f);
        float lmax = 0.f;
        #pragma unroll
        for (int mi = 0; mi < 2; mi++) {
            int r0 = mBase + m_w + mi * 16 + (lane >> 2);
            #pragma unroll
            for (int nj = 0; nj < 8; nj++) {
                int c0 = nBase + n_w + nj * 8 + (lane & 3) * 2;
                float b0 = bias[c0], b1 = bias[c0 + 1];
                float g00 = gelu_erf(acc[mi][nj][0] * scale + b0);
                float g01 = gelu_erf(acc[mi][nj][1] * scale + b1);
                float g10 = gelu_erf(acc[mi][nj][2] * scale + b0);
                float g11 = gelu_erf(acc[mi][nj][3] * scale + b1);
                *(float2*)&g_act[(size_t)r0 * N + c0]       = make_float2(g00, g01);
                *(float2*)&g_act[(size_t)(r0 + 8) * N + c0] = make_float2(g10, g11);
                lmax = fmaxf(lmax, fmaxf(fmaxf(fabsf(g00), fabsf(g01)),
                                         fmaxf(fabsf(g10), fabsf(g11))));
            }
        }
        #pragma unroll
        for (int o = 16; o; o >>= 1) lmax = fmaxf(lmax, __shfl_xor_sync(0xffffffffu, lmax, o));
        if (lane == 0) atomicMax(&g_maxbits[3], __float_as_uint(lmax));
    } else {
        float sG = __uint_as_float(g_maxbits[3]);
        float sW = __uint_as_float(g_maxbits[2]);
        float scale = sG * sW * (1.0f / 16129.0f);
        #pragma unroll
        for (int mi = 0; mi < 2; mi++) {
            int r0 = mBase + m_w + mi * 16 + (lane >> 2);
            #pragma unroll
            for (int nj = 0; nj < 8; nj++) {
                int c0 = nBase + n_w + nj * 8 + (lane & 3) * 2;
                float b0 = bias[c0], b1 = bias[c0 + 1];
                float y00 = acc[mi][nj][0] * scale + b0;
                float y01 = acc[mi][nj][1] * scale + b1;
                float y10 = acc[mi][nj][2] * scale + b0;
                float y11 = acc[mi][nj][3] * scale + b1;
                *(float2*)&out[(size_t)r0 * N + c0]       = make_float2(y00, y01);
                *(float2*)&out[(size_t)(r0 + 8) * N + c0] = make_float2(y10, y11);
            }
        }
    }
}

// ---------------- launch ----------------
extern "C" void kernel_launch(void* const* d_in, const int* in_sizes, int n_in,
                              void* d_out, int out_size) {
    const float* x     = (const float*)d_in[0];
    const float* gamma = (const float*)d_in[1];
    const float* beta  = (const float*)d_in[2];
    const float* w1    = (const float*)d_in[3];
    const float* b1    = (const float*)d_in[4];
    const float* w2    = (const float*)d_in[5];
    const float* b2    = (const float*)d_in[6];
    float* out = (float*)d_out;

    const int WN4 = HID * DIM / 4;  // 1048576 float4s per weight matrix

    k_init<<<1, 32>>>();
    k_maxabs<<<512, 256>>>((const float4*)w1, WN4, 1);
    k_maxabs<<<512, 256>>>((const float4*)w2, WN4, 2);
    k_ln<<<NROWS, 256>>>(x, gamma, beta);
    k_wquant<<<WN4 / 256, 256>>>((const float4*)w1, WN4, 1);
    k_wquant<<<WN4 / 256, 256>>>((const float4*)w2, WN4, 2);
    k_aquant<<<NROWS * (DIM / 4) / 256, 256>>>(x, gamma, beta);

    // GEMM1: [32768 x 1024] x [4096 x 1024]^T -> gelu -> g_act, track max|gelu|
    k_gemm<true, HID, DIM><<<dim3(HID / 128, NROWS / 128), 256>>>(b1, nullptr);

    k_hquant<<<NROWS * (HID / 4) / 256, 256>>>();

    // GEMM2: [32768 x 4096] x [1024 x 4096]^T -> d_out
    k_gemm<false, DIM, HID><<<dim3(DIM / 128, NROWS / 128), 256>>>(b2, out);
}